// round 1
// baseline (speedup 1.0000x reference)
#include <cuda_runtime.h>

#define IMG_W  512
#define IMG_H  512
#define TILE_X 128
#define TILE_Y 128
#define HALO   5
#define NITER  (TILE_Y + 2 * HALO)   /* 138 h-conv rows per tile */
#define ROW_PAD 144                  /* 138 used, padded */

// Normalized 11-tap Gaussian, sigma=1.5, center at ws/2=5.5 (matches torch/ref:
// exp(-(i-5.5)^2/(2*1.5^2)) / sum). Hardcoded so ptxas emits FFMA-imm (rt=1).
__device__ constexpr float GW[11] = {
    3.2030000e-04f, 2.9556500e-03f, 1.7487670e-02f, 6.6342420e-02f,
    1.6137299e-01f, 2.5168110e-01f, 2.5168110e-01f, 1.6137299e-01f,
    6.6342420e-02f, 1.7487670e-02f, 2.9556500e-03f
};

// ---------------------------------------------------------------------------
// Global min/max of img1 (for dynamic range -> C1, C2)
// ---------------------------------------------------------------------------
__device__ unsigned g_max_enc;
__device__ unsigned g_min_enc;

__device__ __forceinline__ unsigned enc_f(float f) {
    unsigned u = __float_as_uint(f);
    return (u & 0x80000000u) ? ~u : (u | 0x80000000u);  // monotonic float->uint
}
__device__ __forceinline__ float dec_f(unsigned e) {
    unsigned u = (e & 0x80000000u) ? (e ^ 0x80000000u) : ~e;
    return __uint_as_float(u);
}

__global__ void init_minmax_kernel() {
    g_max_enc = 0u;
    g_min_enc = 0xFFFFFFFFu;
}

__global__ void minmax_kernel(const float4* __restrict__ x, int n4) {
    float mx = -3.402823466e38f, mn = 3.402823466e38f;
    const int stride = gridDim.x * blockDim.x;
    for (int i = blockIdx.x * blockDim.x + threadIdx.x; i < n4; i += stride) {
        float4 v = x[i];
        mx = fmaxf(mx, fmaxf(fmaxf(v.x, v.y), fmaxf(v.z, v.w)));
        mn = fminf(mn, fminf(fminf(v.x, v.y), fminf(v.z, v.w)));
    }
#pragma unroll
    for (int o = 16; o > 0; o >>= 1) {
        mx = fmaxf(mx, __shfl_xor_sync(0xFFFFFFFFu, mx, o));
        mn = fminf(mn, __shfl_xor_sync(0xFFFFFFFFu, mn, o));
    }
    __shared__ float smx[8], smn[8];
    const int w = threadIdx.x >> 5, l = threadIdx.x & 31;
    if (l == 0) { smx[w] = mx; smn[w] = mn; }
    __syncthreads();
    if (threadIdx.x == 0) {
        const int nw = blockDim.x >> 5;
        for (int k = 1; k < nw; ++k) { mx = fmaxf(mx, smx[k]); mn = fminf(mn, smn[k]); }
        atomicMax(&g_max_enc, enc_f(mx));
        atomicMin(&g_min_enc, enc_f(mn));
    }
}

// ---------------------------------------------------------------------------
// Fused separable-SSIM kernel
// ---------------------------------------------------------------------------
__device__ __forceinline__ void load_row(const float* __restrict__ p1,
                                         const float* __restrict__ p2,
                                         int hy, int x0, int tx,
                                         float& v1a, float& v1b,
                                         float& v2a, float& v2b) {
    v1a = 0.f; v1b = 0.f; v2a = 0.f; v2b = 0.f;
    if ((unsigned)hy < (unsigned)IMG_H) {
        const float* r1 = p1 + hy * IMG_W;
        const float* r2 = p2 + hy * IMG_W;
        const int cA = x0 - HALO + tx;
        if ((unsigned)cA < (unsigned)IMG_W) { v1a = __ldg(r1 + cA); v2a = __ldg(r2 + cA); }
        const int cB = cA + TILE_X;
        if (tx < 2 * HALO && (unsigned)cB < (unsigned)IMG_W) {
            v1b = __ldg(r1 + cB); v2b = __ldg(r2 + cB);
        }
    }
}

__global__ void __launch_bounds__(TILE_X)
ssim_kernel(const float* __restrict__ img1, const float* __restrict__ img2,
            float* __restrict__ out) {
    const int tx = threadIdx.x;
    const int x0 = blockIdx.x * TILE_X;
    const int y0 = blockIdx.y * TILE_Y;
    const long imgoff = (long)blockIdx.z * (IMG_W * IMG_H);
    const float* p1 = img1 + imgoff;
    const float* p2 = img2 + imgoff;
    float* po = out + imgoff;

    float L = dec_f(g_max_enc) - dec_f(g_min_enc);
    if (L == 0.f) L = 5.f;
    const float C1 = (0.01f * L) * (0.01f * L);
    const float C2 = (0.03f * L) * (0.03f * L);

    __shared__ float s1[2][ROW_PAD];
    __shared__ float s2[2][ROW_PAD];

    // Vertical rolling window: 5 channels x 11 rows, register-resident.
    // All indices compile-time via unroll-by-11 (NITER rows, ring period 11).
    float wm1[11], wm2[11], w11[11], w22[11], w12[11];
#pragma unroll
    for (int k = 0; k < 11; ++k) {
        wm1[k] = 0.f; wm2[k] = 0.f; w11[k] = 0.f; w22[k] = 0.f; w12[k] = 0.f;
    }

    float pf1a, pf1b, pf2a, pf2b;
    load_row(p1, p2, y0 - HALO, x0, tx, pf1a, pf1b, pf2a, pf2b);

    for (int ib = 0; ib < NITER; ib += 11) {
#pragma unroll
        for (int j = 0; j < 11; ++j) {
            const int i = ib + j;          // ib % 11 == 0, so ring slot == j
            if (i < NITER) {
                const int buf = i & 1;
                // publish prefetched row
                s1[buf][tx] = pf1a; s2[buf][tx] = pf2a;
                if (tx < 2 * HALO) { s1[buf][TILE_X + tx] = pf1b; s2[buf][TILE_X + tx] = pf2b; }
                __syncthreads();
                // software prefetch next row (overlaps with compute below)
                load_row(p1, p2, y0 - HALO + i + 1, x0, tx, pf1a, pf1b, pf2a, pf2b);

                // horizontal 11-tap pass, 5 channels; products formed in regs
                float h0 = 0.f, h1 = 0.f, h2 = 0.f, h3 = 0.f, h4 = 0.f;
#pragma unroll
                for (int k = 0; k < 11; ++k) {
                    const float a = s1[buf][tx + k];
                    const float b = s2[buf][tx + k];
                    h0 = fmaf(a,     GW[k], h0);
                    h1 = fmaf(b,     GW[k], h1);
                    h2 = fmaf(a * a, GW[k], h2);
                    h3 = fmaf(b * b, GW[k], h3);
                    h4 = fmaf(a * b, GW[k], h4);
                }
                wm1[j] = h0; wm2[j] = h1; w11[j] = h2; w22[j] = h3; w12[j] = h4;

                if (i >= 2 * HALO) {
                    // vertical 11-tap pass over the register ring
                    float mu1 = 0.f, mu2 = 0.f, vx11 = 0.f, vx22 = 0.f, vx12 = 0.f;
#pragma unroll
                    for (int k = 0; k < 11; ++k) {
                        const int s = (j + 1 + k) % 11;   // compile-time
                        mu1  = fmaf(wm1[s], GW[k], mu1);
                        mu2  = fmaf(wm2[s], GW[k], mu2);
                        vx11 = fmaf(w11[s], GW[k], vx11);
                        vx22 = fmaf(w22[s], GW[k], vx22);
                        vx12 = fmaf(w12[s], GW[k], vx12);
                    }
                    const float mu1sq = mu1 * mu1;
                    const float mu2sq = mu2 * mu2;
                    const float mu12  = mu1 * mu2;
                    const float sig1  = vx11 - mu1sq;
                    const float sig2  = vx22 - mu2sq;
                    const float sig12 = vx12 - mu12;
                    const float num = fmaf(2.f, mu12,  C1) * fmaf(2.f, sig12, C2);
                    const float den = (mu1sq + mu2sq + C1) * (sig1 + sig2 + C2);
                    const int y = y0 + i - 2 * HALO;
                    po[y * IMG_W + x0 + tx] = __fdividef(num, den);
                }
            }
        }
    }
}

// ---------------------------------------------------------------------------
extern "C" void kernel_launch(void* const* d_in, const int* in_sizes, int n_in,
                              void* d_out, int out_size) {
    const float* img1 = (const float*)d_in[0];
    const float* img2 = (const float*)d_in[1];
    float* out = (float*)d_out;
    const int n = in_sizes[0];                 // 32*1*512*512 = 8388608

    init_minmax_kernel<<<1, 1>>>();
    minmax_kernel<<<512, 256>>>((const float4*)img1, n / 4);

    dim3 grid(IMG_W / TILE_X, IMG_H / TILE_Y, n / (IMG_W * IMG_H));  // (4,4,32)
    ssim_kernel<<<grid, TILE_X>>>(img1, img2, out);
}

// round 2
// speedup vs baseline: 1.0312x; 1.0312x over previous
#include <cuda_runtime.h>

#define IMG_W  512
#define IMG_H  512
#define IMG_N  (IMG_W * IMG_H)
#define TILE_X 128
#define TILE_Y 64
#define HALO   5
#define NITER  (TILE_Y + 2 * HALO)   /* 74 h-conv rows per tile */
#define ROW_PAD 144
#define MM_BLOCKS 512
#define MM_THREADS 256

// Normalized 11-tap Gaussian, sigma=1.5, center at ws/2=5.5 (matches ref).
// GW[k] == GW[11-k] for k=1..10; GW[0] unique. Literals -> FFMA-imm forms.
__device__ constexpr float GW[11] = {
    3.2030000e-04f, 2.9556500e-03f, 1.7487670e-02f, 6.6342420e-02f,
    1.6137299e-01f, 2.5168110e-01f, 2.5168110e-01f, 1.6137299e-01f,
    6.6342420e-02f, 1.7487670e-02f, 2.9556500e-03f
};

// ---------------------------------------------------------------------------
// packed f32x2 helpers (sm_103a FFMA2/FMUL2 via PTX)
// ---------------------------------------------------------------------------
typedef unsigned long long u64;

__device__ __forceinline__ u64 pack2(float x, float y) {
    u64 r; asm("mov.b64 %0, {%1, %2};" : "=l"(r) : "f"(x), "f"(y)); return r;
}
__device__ __forceinline__ void unpack2(u64 v, float& x, float& y) {
    asm("mov.b64 {%0, %1}, %2;" : "=f"(x), "=f"(y) : "l"(v));
}
__device__ __forceinline__ u64 fma2(u64 a, u64 b, u64 c) {
    u64 d; asm("fma.rn.f32x2 %0, %1, %2, %3;" : "=l"(d) : "l"(a), "l"(b), "l"(c));
    return d;
}
__device__ __forceinline__ u64 mul2(u64 a, u64 b) {
    u64 d; asm("mul.rn.f32x2 %0, %1, %2;" : "=l"(d) : "l"(a), "l"(b));
    return d;
}

// ---------------------------------------------------------------------------
// Single-kernel global min/max of img1 -> C1, C2 (last-block finalize,
// self-resetting counter => graph-replay safe, deterministic)
// ---------------------------------------------------------------------------
__device__ float g_blk_max[MM_BLOCKS];
__device__ float g_blk_min[MM_BLOCKS];
__device__ unsigned g_arrive = 0;
__device__ float g_C1, g_C2;

__global__ void __launch_bounds__(MM_THREADS)
minmax_kernel(const float4* __restrict__ x, int n4) {
    float mx = -3.402823466e38f, mn = 3.402823466e38f;
    const int stride = gridDim.x * blockDim.x;
    for (int i = blockIdx.x * blockDim.x + threadIdx.x; i < n4; i += stride) {
        float4 v = x[i];
        mx = fmaxf(mx, fmaxf(fmaxf(v.x, v.y), fmaxf(v.z, v.w)));
        mn = fminf(mn, fminf(fminf(v.x, v.y), fminf(v.z, v.w)));
    }
#pragma unroll
    for (int o = 16; o > 0; o >>= 1) {
        mx = fmaxf(mx, __shfl_xor_sync(0xFFFFFFFFu, mx, o));
        mn = fminf(mn, __shfl_xor_sync(0xFFFFFFFFu, mn, o));
    }
    __shared__ float smx[8], smn[8];
    __shared__ bool last;
    const int w = threadIdx.x >> 5, l = threadIdx.x & 31;
    if (l == 0) { smx[w] = mx; smn[w] = mn; }
    __syncthreads();
    if (threadIdx.x == 0) {
#pragma unroll
        for (int k = 1; k < MM_THREADS / 32; ++k) {
            mx = fmaxf(mx, smx[k]); mn = fminf(mn, smn[k]);
        }
        g_blk_max[blockIdx.x] = mx;
        g_blk_min[blockIdx.x] = mn;
        __threadfence();
        last = (atomicAdd(&g_arrive, 1u) == (unsigned)(gridDim.x - 1));
    }
    __syncthreads();
    if (last) {
        // 256 threads reduce 512 slots
        float fx = fmaxf(g_blk_max[threadIdx.x], g_blk_max[threadIdx.x + 256]);
        float fn = fminf(g_blk_min[threadIdx.x], g_blk_min[threadIdx.x + 256]);
#pragma unroll
        for (int o = 16; o > 0; o >>= 1) {
            fx = fmaxf(fx, __shfl_xor_sync(0xFFFFFFFFu, fx, o));
            fn = fminf(fn, __shfl_xor_sync(0xFFFFFFFFu, fn, o));
        }
        if (l == 0) { smx[w] = fx; smn[w] = fn; }
        __syncthreads();
        if (threadIdx.x == 0) {
#pragma unroll
            for (int k = 1; k < MM_THREADS / 32; ++k) {
                fx = fmaxf(fx, smx[k]); fn = fminf(fn, smn[k]);
            }
            float L = fx - fn;
            if (L == 0.f) L = 5.f;
            g_C1 = (0.01f * L) * (0.01f * L);
            g_C2 = (0.03f * L) * (0.03f * L);
            g_arrive = 0;   // reset for next graph replay
        }
    }
}

// ---------------------------------------------------------------------------
// Fused separable-SSIM kernel (packed f32x2 datapath)
// ---------------------------------------------------------------------------
__device__ __forceinline__ void load_row(const float* __restrict__ p1,
                                         const float* __restrict__ p2,
                                         int hy, int x0, int tx,
                                         float2& va, float2& vb) {
    va = make_float2(0.f, 0.f);
    vb = make_float2(0.f, 0.f);
    if ((unsigned)hy < (unsigned)IMG_H) {
        const int r = hy * IMG_W;
        const int cA = x0 - HALO + tx;
        if ((unsigned)cA < (unsigned)IMG_W)
            va = make_float2(__ldg(p1 + r + cA), __ldg(p2 + r + cA));
        const int cB = cA + TILE_X;
        if (tx < 2 * HALO && (unsigned)cB < (unsigned)IMG_W)
            vb = make_float2(__ldg(p1 + r + cB), __ldg(p2 + r + cB));
    }
}

__global__ void __launch_bounds__(TILE_X, 5)
ssim_kernel(const float* __restrict__ img1, const float* __restrict__ img2,
            float* __restrict__ out) {
    const int tx = threadIdx.x;
    const int x0 = blockIdx.x * TILE_X;
    const int y0 = blockIdx.y * TILE_Y;
    const long imgoff = (long)blockIdx.z * IMG_N;
    const float* p1 = img1 + imgoff;
    const float* p2 = img2 + imgoff;
    float* po = out + imgoff;

    const float C1 = g_C1;
    const float C2 = g_C2;

    __shared__ float2 sab[2][ROW_PAD];   // (img1, img2) interleaved per column

    // packed tap weights (6 distinct, symmetric)
    u64 WW6[6];
#pragma unroll
    for (int k = 0; k < 6; ++k) WW6[k] = pack2(GW[k], GW[k]);

    // Vertical rolling window: packed (mu1,mu2), packed (x2,y2), scalar xy.
    u64 rm12[11], r1122[11];
    float r12[11];
#pragma unroll
    for (int k = 0; k < 11; ++k) { rm12[k] = 0ull; r1122[k] = 0ull; r12[k] = 0.f; }

    float2 pfa, pfb;
    load_row(p1, p2, y0 - HALO, x0, tx, pfa, pfb);

    for (int ib = 0; ib < NITER; ib += 11) {
#pragma unroll
        for (int j = 0; j < 11; ++j) {
            const int i = ib + j;          // ring slot == j (ib % 11 == 0)
            if (i < NITER) {
                const int buf = i & 1;
                sab[buf][tx] = pfa;
                if (tx < 2 * HALO) sab[buf][TILE_X + tx] = pfb;
                __syncthreads();
                // software prefetch next row (overlaps compute below)
                load_row(p1, p2, y0 - HALO + i + 1, x0, tx, pfa, pfb);

                // horizontal 11-tap pass, packed channels
                u64 h01 = 0ull, h23 = 0ull;
                float h4 = 0.f;
#pragma unroll
                for (int k = 0; k < 11; ++k) {
                    const int kk = (k <= 5) ? k : (11 - k);
                    const u64 p = *reinterpret_cast<const u64*>(&sab[buf][tx + k]);
                    h01 = fma2(p, WW6[kk], h01);        // (Σw·a, Σw·b)
                    const u64 pp = mul2(p, p);          // (a², b²)
                    h23 = fma2(pp, WW6[kk], h23);       // (Σw·a², Σw·b²)
                    float a, b; unpack2(p, a, b);
                    h4 = fmaf(a * b, GW[k], h4);        // Σw·ab
                }
                rm12[j] = h01; r1122[j] = h23; r12[j] = h4;

                if (i >= 2 * HALO) {
                    // vertical 11-tap pass over the register ring
                    u64 M = 0ull, S = 0ull;
                    float s12 = 0.f;
#pragma unroll
                    for (int k = 0; k < 11; ++k) {
                        const int s = (j + 1 + k) % 11;         // compile-time
                        const int kk = (k <= 5) ? k : (11 - k);
                        M   = fma2(rm12[s],  WW6[kk], M);
                        S   = fma2(r1122[s], WW6[kk], S);
                        s12 = fmaf(r12[s], GW[k], s12);
                    }
                    float mu1, mu2, e11, e22;
                    unpack2(M, mu1, mu2);
                    unpack2(S, e11, e22);
                    const float mu1sq = mu1 * mu1;
                    const float mu2sq = mu2 * mu2;
                    const float mu12  = mu1 * mu2;
                    const float sig1  = e11 - mu1sq;
                    const float sig2  = e22 - mu2sq;
                    const float sig12 = s12 - mu12;
                    const float num = fmaf(2.f, mu12,  C1) * fmaf(2.f, sig12, C2);
                    const float den = (mu1sq + mu2sq + C1) * (sig1 + sig2 + C2);
                    const int y = y0 + i - 2 * HALO;
                    po[y * IMG_W + x0 + tx] = __fdividef(num, den);
                }
            }
        }
    }
}

// ---------------------------------------------------------------------------
extern "C" void kernel_launch(void* const* d_in, const int* in_sizes, int n_in,
                              void* d_out, int out_size) {
    const float* img1 = (const float*)d_in[0];
    const float* img2 = (const float*)d_in[1];
    float* out = (float*)d_out;
    const int n = in_sizes[0];                 // 32*1*512*512 = 8388608

    minmax_kernel<<<MM_BLOCKS, MM_THREADS>>>((const float4*)img1, n / 4);

    dim3 grid(IMG_W / TILE_X, IMG_H / TILE_Y, n / IMG_N);   // (4, 8, 32)
    ssim_kernel<<<grid, TILE_X>>>(img1, img2, out);
}

// round 4
// speedup vs baseline: 1.1070x; 1.0735x over previous
#include <cuda_runtime.h>

#define IMG_W  512
#define IMG_H  512
#define IMG_N  (IMG_W * IMG_H)
#define TILE_X 128
#define TILE_Y 64
#define HALO   5
#define NITER  (TILE_Y + 2 * HALO)   /* 74 h-conv rows per tile */
#define ROW_PAD 140
#define MM_BLOCKS 512
#define MM_THREADS 256

// Normalized 11-tap Gaussian, sigma=1.5, center at ws/2=5.5 (matches ref).
__device__ constexpr float GW[11] = {
    3.2030000e-04f, 2.9556500e-03f, 1.7487670e-02f, 6.6342420e-02f,
    1.6137299e-01f, 2.5168110e-01f, 2.5168110e-01f, 1.6137299e-01f,
    6.6342420e-02f, 1.7487670e-02f, 2.9556500e-03f
};

typedef unsigned long long u64;

__device__ __forceinline__ u64 pack2(float x, float y) {
    u64 r; asm("mov.b64 %0, {%1, %2};" : "=l"(r) : "f"(x), "f"(y)); return r;
}
__device__ __forceinline__ void unpack2(u64 v, float& x, float& y) {
    asm("mov.b64 {%0, %1}, %2;" : "=f"(x), "=f"(y) : "l"(v));
}
__device__ __forceinline__ u64 fma2(u64 a, u64 b, u64 c) {
    u64 d; asm("fma.rn.f32x2 %0, %1, %2, %3;" : "=l"(d) : "l"(a), "l"(b), "l"(c));
    return d;
}
__device__ __forceinline__ u64 mul2(u64 a, u64 b) {
    u64 d; asm("mul.rn.f32x2 %0, %1, %2;" : "=l"(d) : "l"(a), "l"(b));
    return d;
}

// ---------------------------------------------------------------------------
// Global min/max of img1 -> C1, C2 (single kernel, last-block finalize,
// self-resetting counter => graph-replay safe)
// ---------------------------------------------------------------------------
__device__ float g_blk_max[MM_BLOCKS];
__device__ float g_blk_min[MM_BLOCKS];
__device__ unsigned g_arrive = 0;
__device__ float g_C1, g_C2;

__global__ void __launch_bounds__(MM_THREADS)
minmax_kernel(const float4* __restrict__ x, int n4) {
    float mx = -3.402823466e38f, mn = 3.402823466e38f;
    const int stride = gridDim.x * blockDim.x;
    for (int i = blockIdx.x * blockDim.x + threadIdx.x; i < n4; i += stride) {
        float4 v = x[i];
        mx = fmaxf(mx, fmaxf(fmaxf(v.x, v.y), fmaxf(v.z, v.w)));
        mn = fminf(mn, fminf(fminf(v.x, v.y), fminf(v.z, v.w)));
    }
#pragma unroll
    for (int o = 16; o > 0; o >>= 1) {
        mx = fmaxf(mx, __shfl_xor_sync(0xFFFFFFFFu, mx, o));
        mn = fminf(mn, __shfl_xor_sync(0xFFFFFFFFu, mn, o));
    }
    __shared__ float smx[8], smn[8];
    __shared__ bool last;
    const int w = threadIdx.x >> 5, l = threadIdx.x & 31;
    if (l == 0) { smx[w] = mx; smn[w] = mn; }
    __syncthreads();
    if (threadIdx.x == 0) {
#pragma unroll
        for (int k = 1; k < MM_THREADS / 32; ++k) {
            mx = fmaxf(mx, smx[k]); mn = fminf(mn, smn[k]);
        }
        g_blk_max[blockIdx.x] = mx;
        g_blk_min[blockIdx.x] = mn;
        __threadfence();
        last = (atomicAdd(&g_arrive, 1u) == (unsigned)(gridDim.x - 1));
    }
    __syncthreads();
    if (last) {
        float fx = fmaxf(g_blk_max[threadIdx.x], g_blk_max[threadIdx.x + 256]);
        float fn = fminf(g_blk_min[threadIdx.x], g_blk_min[threadIdx.x + 256]);
#pragma unroll
        for (int o = 16; o > 0; o >>= 1) {
            fx = fmaxf(fx, __shfl_xor_sync(0xFFFFFFFFu, fx, o));
            fn = fminf(fn, __shfl_xor_sync(0xFFFFFFFFu, fn, o));
        }
        if (l == 0) { smx[w] = fx; smn[w] = fn; }
        __syncthreads();
        if (threadIdx.x == 0) {
#pragma unroll
            for (int k = 1; k < MM_THREADS / 32; ++k) {
                fx = fmaxf(fx, smx[k]); fn = fminf(fn, smn[k]);
            }
            float L = fx - fn;
            if (L == 0.f) L = 5.f;
            g_C1 = (0.01f * L) * (0.01f * L);
            g_C2 = (0.03f * L) * (0.03f * L);
            g_arrive = 0;
        }
    }
}

// ---------------------------------------------------------------------------
// Fused separable-SSIM kernel: pair-batched rows, ab precomputed in smem
// ---------------------------------------------------------------------------
__device__ __forceinline__ void load_row(const float* __restrict__ p1,
                                         const float* __restrict__ p2,
                                         int hy, int x0, int tx,
                                         float2& va, float2& vb) {
    va = make_float2(0.f, 0.f);
    vb = make_float2(0.f, 0.f);
    if ((unsigned)hy < (unsigned)IMG_H) {
        const int r = hy * IMG_W;
        const int cA = x0 - HALO + tx;
        if ((unsigned)cA < (unsigned)IMG_W)
            va = make_float2(__ldg(p1 + r + cA), __ldg(p2 + r + cA));
        const int cB = cA + TILE_X;
        if (tx < 2 * HALO && (unsigned)cB < (unsigned)IMG_W)
            vb = make_float2(__ldg(p1 + r + cB), __ldg(p2 + r + cB));
    }
}

__global__ void __launch_bounds__(TILE_X, 5)
ssim_kernel(const float* __restrict__ img1, const float* __restrict__ img2,
            float* __restrict__ out) {
    const int tx = threadIdx.x;
    const int x0 = blockIdx.x * TILE_X;
    const int y0 = blockIdx.y * TILE_Y;
    const long imgoff = (long)blockIdx.z * IMG_N;
    const float* p1 = img1 + imgoff;
    const float* p2 = img2 + imgoff;
    float* po = out + imgoff;

    const float C1 = g_C1;
    const float C2 = g_C2;

    // two alternating buffer-sets, each holding a PAIR of rows
    __shared__ u64   sab[2][2][ROW_PAD];   // (img1, img2) packed per column
    __shared__ float sp [2][2][ROW_PAD];   // a*b per column

    // packed tap weights (6 distinct, symmetric)
    u64 WW6[6];
#pragma unroll
    for (int k = 0; k < 6; ++k) WW6[k] = pack2(GW[k], GW[k]);

    // vertical rolling ring: packed (mu1,mu2), packed (x2,y2), scalar xy
    u64 rm12[11], r1122[11];
    float r12[11];
#pragma unroll
    for (int k = 0; k < 11; ++k) { rm12[k] = 0ull; r1122[k] = 0ull; r12[k] = 0.f; }

    float2 A0, B0, A1, B1;
    load_row(p1, p2, y0 - HALO,     x0, tx, A0, B0);
    load_row(p1, p2, y0 - HALO + 1, x0, tx, A1, B1);
    int bs = 0;

#define HPASS(SLOT, RR)                                                        \
    do {                                                                       \
        u64 h01 = 0ull, h23 = 0ull; float h4 = 0.f;                            \
        _Pragma("unroll")                                                      \
        for (int k = 0; k < 11; ++k) {                                         \
            const int kk = (k <= 5) ? k : (11 - k);                            \
            const u64 p  = sab[bs][RR][tx + k];                                \
            const float ab = sp[bs][RR][tx + k];                               \
            h01 = fma2(p, WW6[kk], h01);                                       \
            h23 = fma2(mul2(p, p), WW6[kk], h23);                              \
            h4  = fmaf(ab, GW[k], h4);                                         \
        }                                                                      \
        rm12[SLOT] = h01; r1122[SLOT] = h23; r12[SLOT] = h4;                   \
    } while (0)

#define VPASS(SLOT, ROW)                                                       \
    do {                                                                       \
        u64 M = 0ull, S = 0ull; float s12 = 0.f;                               \
        _Pragma("unroll")                                                      \
        for (int k = 0; k < 11; ++k) {                                         \
            const int s  = ((SLOT) + 1 + k) % 11;                              \
            const int kk = (k <= 5) ? k : (11 - k);                            \
            M   = fma2(rm12[s],  WW6[kk], M);                                  \
            S   = fma2(r1122[s], WW6[kk], S);                                  \
            s12 = fmaf(r12[s], GW[k], s12);                                    \
        }                                                                      \
        float mu1, mu2, e11, e22;                                              \
        unpack2(M, mu1, mu2); unpack2(S, e11, e22);                            \
        const float mu1sq = mu1 * mu1;                                         \
        const float mu2sq = mu2 * mu2;                                         \
        const float mu12  = mu1 * mu2;                                         \
        const float num = fmaf(2.f, mu12, C1) * fmaf(2.f, s12 - mu12, C2);     \
        const float den = (mu1sq + mu2sq + C1) *                               \
                          ((e11 - mu1sq) + (e22 - mu2sq) + C2);                \
        po[(y0 + (ROW) - 2 * HALO) * IMG_W + x0 + tx] = __fdividef(num, den);  \
    } while (0)

    for (int ib = 0; ib < NITER; ib += 22) {
#pragma unroll
        for (int jj = 0; jj < 11; ++jj) {
            const int i0 = ib + 2 * jj;
            if (i0 < NITER) {
                // publish prefetched pair (values + a*b products)
                sab[bs][0][tx] = pack2(A0.x, A0.y);
                sp [bs][0][tx] = A0.x * A0.y;
                sab[bs][1][tx] = pack2(A1.x, A1.y);
                sp [bs][1][tx] = A1.x * A1.y;
                if (tx < 2 * HALO) {
                    sab[bs][0][TILE_X + tx] = pack2(B0.x, B0.y);
                    sp [bs][0][TILE_X + tx] = B0.x * B0.y;
                    sab[bs][1][TILE_X + tx] = pack2(B1.x, B1.y);
                    sp [bs][1][TILE_X + tx] = B1.x * B1.y;
                }
                // prefetch next pair (overlaps with compute after the sync)
                load_row(p1, p2, y0 - HALO + i0 + 2, x0, tx, A0, B0);
                load_row(p1, p2, y0 - HALO + i0 + 3, x0, tx, A1, B1);
                __syncthreads();

                const int s0 = (2 * jj) % 11;       // compile-time
                const int s1 = (2 * jj + 1) % 11;   // compile-time
                HPASS(s0, 0);
                if (i0 >= 2 * HALO) VPASS(s0, i0);
                HPASS(s1, 1);
                if (i0 >= 2 * HALO) VPASS(s1, i0 + 1);
                bs ^= 1;
            }
        }
    }
#undef HPASS
#undef VPASS
}

// ---------------------------------------------------------------------------
extern "C" void kernel_launch(void* const* d_in, const int* in_sizes, int n_in,
                              void* d_out, int out_size) {
    const float* img1 = (const float*)d_in[0];
    const float* img2 = (const float*)d_in[1];
    float* out = (float*)d_out;
    const int n = in_sizes[0];                 // 32*1*512*512 = 8388608

    minmax_kernel<<<MM_BLOCKS, MM_THREADS>>>((const float4*)img1, n / 4);

    dim3 grid(IMG_W / TILE_X, IMG_H / TILE_Y, n / IMG_N);   // (4, 8, 32)
    ssim_kernel<<<grid, TILE_X>>>(img1, img2, out);
}